// round 12
// baseline (speedup 1.0000x reference)
#include <cuda_runtime.h>
#include <cstdint>

// out[src] += feat[dst] * w    ; feat [N,64] f32, E=1e6, N=1e5
// 2-launch slotted pipeline (no histogram, no scan):
//   k_scatter : pos = atomicAdd(&g_len[src],1); if (pos<32) g_edge[src*32+pos]=(dst,w)
//   k_accum   : per-node gather+FMA over its slot; resets g_len for next replay
//
// Slot stride = 32 edges * 8B = 256B. Critical: stride 256B keeps address
// bit 8 (an L2 slice-hash bit) varying with node parity -- a 512B stride
// pins bit 8 to 0 and halves L2 bandwidth (measured 30.5us -> 65us in R10).
// Max degree for this dataset ~ Poisson(10); P(deg>=33) ~ 5e-9/node, and an
// overflow is fail-visible (dropped edge -> rel_err check fails), not silent.
//
// Inputs: d_in[0]=feat f32[N*64], d_in[1]=ew f32[E],
//         d_in[2]=esrc i32[E],    d_in[3]=edst i32[E]

#define MAXN 100000
#define SLOT 32                       // 256B stride per node

__device__ int    g_len[MAXN];                  // cursor == degree; accum resets
__device__ float2 g_edge[(size_t)MAXN * SLOT];  // .x=__int_as_float(dst), .y=w

// 4 edges per thread, vectorized loads, slot-addressed stores.
__global__ void k_scatter(const int4* __restrict__ esrc4,
                          const int4* __restrict__ edst4,
                          const float4* __restrict__ ew4,
                          int n_edges4) {
    int i = blockIdx.x * blockDim.x + threadIdx.x;
    if (i >= n_edges4) return;
    int4   s = __ldg(&esrc4[i]);
    int4   d = __ldg(&edst4[i]);
    float4 w = __ldg(&ew4[i]);
    int p0 = atomicAdd(&g_len[s.x], 1);
    int p1 = atomicAdd(&g_len[s.y], 1);
    int p2 = atomicAdd(&g_len[s.z], 1);
    int p3 = atomicAdd(&g_len[s.w], 1);
    if (p0 < SLOT) g_edge[((size_t)s.x << 5) + p0] = make_float2(__int_as_float(d.x), w.x);
    if (p1 < SLOT) g_edge[((size_t)s.y << 5) + p1] = make_float2(__int_as_float(d.y), w.y);
    if (p2 < SLOT) g_edge[((size_t)s.z << 5) + p2] = make_float2(__int_as_float(d.z), w.z);
    if (p3 < SLOT) g_edge[((size_t)s.w << 5) + p3] = make_float2(__int_as_float(d.w), w.w);
}

// 16 lanes per node, unroll-2 with next-pair prefetch; 8 blocks/SM.
__global__ __launch_bounds__(256, 8) void k_accum(const float* __restrict__ feat,
                                                  float* __restrict__ out,
                                                  int n_nodes) {
    int gid  = blockIdx.x * blockDim.x + threadIdx.x;
    int node = gid >> 4;
    int lane = gid & 15;
    if (node >= n_nodes) return;

    int len = g_len[node];            // broadcast load (16 lanes, same LDG)
    if (lane == 0) g_len[node] = 0;   // reset for next replay
    len = min(len, SLOT);

    const float2* ep = g_edge + ((size_t)node << 5);
    float4 acc = make_float4(0.f, 0.f, 0.f, 0.f);
    int j = 0;

    if (j + 1 < len) {
        float2 e0 = __ldg(&ep[j]);
        float2 e1 = __ldg(&ep[j + 1]);
        for (; j + 3 < len; j += 2) {
            float2 n0 = __ldg(&ep[j + 2]);
            float2 n1 = __ldg(&ep[j + 3]);
            const float4* r0 = reinterpret_cast<const float4*>(feat + (__float_as_int(e0.x) << 6));
            const float4* r1 = reinterpret_cast<const float4*>(feat + (__float_as_int(e1.x) << 6));
            float4 v0 = __ldg(&r0[lane]);
            float4 v1 = __ldg(&r1[lane]);
            acc.x += v0.x * e0.y + v1.x * e1.y;
            acc.y += v0.y * e0.y + v1.y * e1.y;
            acc.z += v0.z * e0.y + v1.z * e1.y;
            acc.w += v0.w * e0.y + v1.w * e1.y;
            e0 = n0; e1 = n1;
        }
        const float4* r0 = reinterpret_cast<const float4*>(feat + (__float_as_int(e0.x) << 6));
        const float4* r1 = reinterpret_cast<const float4*>(feat + (__float_as_int(e1.x) << 6));
        float4 v0 = __ldg(&r0[lane]);
        float4 v1 = __ldg(&r1[lane]);
        acc.x += v0.x * e0.y + v1.x * e1.y;
        acc.y += v0.y * e0.y + v1.y * e1.y;
        acc.z += v0.z * e0.y + v1.z * e1.y;
        acc.w += v0.w * e0.y + v1.w * e1.y;
        j += 2;
    }
    if (j < len) {
        float2 e0 = __ldg(&ep[j]);
        const float4* r0 = reinterpret_cast<const float4*>(feat + (__float_as_int(e0.x) << 6));
        float4 v0 = __ldg(&r0[lane]);
        acc.x += v0.x * e0.y;
        acc.y += v0.y * e0.y;
        acc.z += v0.z * e0.y;
        acc.w += v0.w * e0.y;
    }
    reinterpret_cast<float4*>(out + ((long long)node << 6))[lane] = acc;
}

extern "C" void kernel_launch(void* const* d_in, const int* in_sizes, int n_in,
                              void* d_out, int out_size)
{
    const float* feat = (const float*)d_in[0];
    const float* ew   = (const float*)d_in[1];
    const int*   esrc = (const int*)d_in[2];
    const int*   edst = (const int*)d_in[3];
    float*       out  = (float*)d_out;

    int n_edges  = in_sizes[1];
    int n_nodes  = out_size / 64;
    int n_edges4 = n_edges / 4;   // E divisible by 4

    k_scatter<<<(n_edges4 + 255) / 256, 256>>>((const int4*)esrc, (const int4*)edst,
                                               (const float4*)ew, n_edges4);

    long long total = (long long)n_nodes * 16;
    k_accum<<<(int)((total + 255) / 256), 256>>>(feat, out, n_nodes);
}

// round 13
// speedup vs baseline: 1.3439x; 1.3439x over previous
#include <cuda_runtime.h>
#include <cstdint>

// out[src] += feat[dst] * w    ; feat [N,64] f32, E=1e6, N=1e5
// 2-launch pipeline:
//   k_build : persistent, 148 blocks x 1024 (1/SM, co-resident):
//             hist -> barrier -> order-free scan -> barrier -> scatter
//   k_accum : atomic-free per-node gather+FMA (UNCHANGED proven R11 loop);
//             resets g_total for the next graph replay
//
// Inputs: d_in[0]=feat f32[N*64], d_in[1]=ew f32[E],
//         d_in[2]=esrc i32[E],    d_in[3]=edst i32[E]

#define MAXN 100000
#define MAXE 1000000
#define NBLK 148                 // one block per SM, guaranteed co-resident
#define BTHR 1024
#define SCAN_CHUNK 1024

__device__ int      g_cnt[MAXN];     // zero at entry (zero-init; scan resets)
__device__ int2     g_desc[MAXN];    // {start, len}
__device__ int      g_cursor[MAXN];
__device__ float2   g_edge[MAXE];    // dense CSR payload
__device__ unsigned g_total;         // base allocator; accum resets
__device__ unsigned g_tick[2];       // monotonic barrier tickets (replay-safe)

// Release-acquire grid barrier; poll via plain volatile load (no atomic spin).
__device__ __forceinline__ void grid_barrier(int which) {
    __syncthreads();
    if (threadIdx.x == 0) {
        __threadfence();                               // release
        unsigned ticket = atomicAdd(&g_tick[which], 1u);
        unsigned target = (ticket / NBLK + 1u) * NBLK;
        while (*(volatile unsigned*)&g_tick[which] < target) { }
        __threadfence();                               // acquire
    }
    __syncthreads();
}

__global__ __launch_bounds__(BTHR, 1) void k_build(
    const int4*   __restrict__ esrc4,
    const int4*   __restrict__ edst4,
    const float4* __restrict__ ew4,
    int n_edges4, int n)
{
    int b = blockIdx.x, t = threadIdx.x;
    int gtid   = b * BTHR + t;
    int stride = NBLK * BTHR;

    // ---- phase 1: degree histogram (grid-stride, full chip) ----
    for (int i = gtid; i < n_edges4; i += stride) {
        int4 s = __ldg(&esrc4[i]);
        atomicAdd(&g_cnt[s.x], 1);
        atomicAdd(&g_cnt[s.y], 1);
        atomicAdd(&g_cnt[s.z], 1);
        atomicAdd(&g_cnt[s.w], 1);
    }
    grid_barrier(0);

    // ---- phase 2: order-free scan (blocks 0..97 own 1024-node chunks) ----
    {
        __shared__ int warp_sum[32];
        __shared__ int s_base;
        int lane = t & 31, w = t >> 5;
        int i = b * SCAN_CHUNK + t;             // blocks >= 98 fall out (i >= n)

        int v = 0;
        if (i < n) { v = g_cnt[i]; g_cnt[i] = 0; }

        int x = v;
        #pragma unroll
        for (int off = 1; off < 32; off <<= 1) {
            int y = __shfl_up_sync(0xffffffff, x, off);
            if (lane >= off) x += y;
        }
        if (lane == 31) warp_sum[w] = x;
        __syncthreads();

        if (w == 0) {
            int ws = warp_sum[lane];
            int z = ws;
            #pragma unroll
            for (int off = 1; off < 32; off <<= 1) {
                int y = __shfl_up_sync(0xffffffff, z, off);
                if (lane >= off) z += y;
            }
            warp_sum[lane] = z - ws;            // exclusive warp offsets
            if (lane == 31) s_base = (int)atomicAdd(&g_total, (unsigned)z);
        }
        __syncthreads();

        if (i < n) {
            int start = s_base + warp_sum[w] + (x - v);
            g_desc[i]   = make_int2(start, v);
            g_cursor[i] = start;
        }
    }
    grid_barrier(1);

    // ---- phase 3: scatter (dst, w) into dense CSR order ----
    for (int j = gtid; j < n_edges4; j += stride) {
        int4   s  = __ldg(&esrc4[j]);
        int4   d  = __ldg(&edst4[j]);
        float4 wt = __ldg(&ew4[j]);
        int p0 = atomicAdd(&g_cursor[s.x], 1);
        int p1 = atomicAdd(&g_cursor[s.y], 1);
        int p2 = atomicAdd(&g_cursor[s.z], 1);
        int p3 = atomicAdd(&g_cursor[s.w], 1);
        g_edge[p0] = make_float2(__int_as_float(d.x), wt.x);
        g_edge[p1] = make_float2(__int_as_float(d.y), wt.y);
        g_edge[p2] = make_float2(__int_as_float(d.z), wt.z);
        g_edge[p3] = make_float2(__int_as_float(d.w), wt.w);
    }
}

// 16 lanes per node, unroll-2 with next-pair prefetch; 8 blocks/SM. (R11 loop.)
__global__ __launch_bounds__(256, 8) void k_accum(const float* __restrict__ feat,
                                                  float* __restrict__ out,
                                                  int n_nodes) {
    int gid  = blockIdx.x * blockDim.x + threadIdx.x;
    int node = gid >> 4;
    int lane = gid & 15;
    if (gid == 0) g_total = 0;          // reset allocator for next replay
    if (node >= n_nodes) return;

    int2 dsc = __ldg(&g_desc[node]);    // one 8B broadcast load: {start, len}
    int beg = dsc.x;
    int end = dsc.x + dsc.y;

    float4 acc = make_float4(0.f, 0.f, 0.f, 0.f);
    int j = beg;

    if (j + 1 < end) {
        float2 e0 = __ldg(&g_edge[j]);
        float2 e1 = __ldg(&g_edge[j + 1]);
        for (; j + 3 < end; j += 2) {
            float2 n0 = __ldg(&g_edge[j + 2]);
            float2 n1 = __ldg(&g_edge[j + 3]);
            const float4* r0 = reinterpret_cast<const float4*>(feat + (__float_as_int(e0.x) << 6));
            const float4* r1 = reinterpret_cast<const float4*>(feat + (__float_as_int(e1.x) << 6));
            float4 v0 = __ldg(&r0[lane]);
            float4 v1 = __ldg(&r1[lane]);
            acc.x += v0.x * e0.y + v1.x * e1.y;
            acc.y += v0.y * e0.y + v1.y * e1.y;
            acc.z += v0.z * e0.y + v1.z * e1.y;
            acc.w += v0.w * e0.y + v1.w * e1.y;
            e0 = n0; e1 = n1;
        }
        const float4* r0 = reinterpret_cast<const float4*>(feat + (__float_as_int(e0.x) << 6));
        const float4* r1 = reinterpret_cast<const float4*>(feat + (__float_as_int(e1.x) << 6));
        float4 v0 = __ldg(&r0[lane]);
        float4 v1 = __ldg(&r1[lane]);
        acc.x += v0.x * e0.y + v1.x * e1.y;
        acc.y += v0.y * e0.y + v1.y * e1.y;
        acc.z += v0.z * e0.y + v1.z * e1.y;
        acc.w += v0.w * e0.y + v1.w * e1.y;
        j += 2;
    }
    if (j < end) {
        float2 e0 = __ldg(&g_edge[j]);
        const float4* r0 = reinterpret_cast<const float4*>(feat + (__float_as_int(e0.x) << 6));
        float4 v0 = __ldg(&r0[lane]);
        acc.x += v0.x * e0.y;
        acc.y += v0.y * e0.y;
        acc.z += v0.z * e0.y;
        acc.w += v0.w * e0.y;
    }
    reinterpret_cast<float4*>(out + ((long long)node << 6))[lane] = acc;
}

extern "C" void kernel_launch(void* const* d_in, const int* in_sizes, int n_in,
                              void* d_out, int out_size)
{
    const float* feat = (const float*)d_in[0];
    const float* ew   = (const float*)d_in[1];
    const int*   esrc = (const int*)d_in[2];
    const int*   edst = (const int*)d_in[3];
    float*       out  = (float*)d_out;

    int n_edges  = in_sizes[1];
    int n_nodes  = out_size / 64;
    int n_edges4 = n_edges / 4;   // E divisible by 4

    k_build<<<NBLK, BTHR>>>((const int4*)esrc, (const int4*)edst,
                            (const float4*)ew, n_edges4, n_nodes);

    long long total = (long long)n_nodes * 16;
    k_accum<<<(int)((total + 255) / 256), 256>>>(feat, out, n_nodes);
}

// round 14
// speedup vs baseline: 1.3849x; 1.0305x over previous
#include <cuda_runtime.h>
#include <cstdint>

// out[src] += feat[dst] * w    ; feat [N,64] f32, E=1e6, N=1e5
// 4-launch dense-CSR pipeline (R11 structure, proven fastest):
//   k_hist   : degree histogram (atomics)
//   k_scan   : per-block scan; block base via ONE global atomicAdd (order-free)
//   k_scatter: permute (dst,w) into dense CSR order via cursor atomics
//   k_accum  : atomic-free gather+FMA, ONE FULL WARP PER NODE (zero divergence)
//
// Inputs: d_in[0]=feat f32[N*64], d_in[1]=ew f32[E],
//         d_in[2]=esrc i32[E],    d_in[3]=edst i32[E]

#define MAXN 100000
#define MAXE 1000000
#define SCAN_CHUNK 1024

__device__ int      g_cnt[MAXN];     // zero at entry (zero-init; k_scan resets)
__device__ int2     g_desc[MAXN];    // {start, len} per node
__device__ int      g_cursor[MAXN];
__device__ float2   g_edge[MAXE];    // dense; .x = __int_as_float(dst), .y = w
__device__ unsigned g_total;         // base allocator; accum resets

__global__ void k_hist(const int4* __restrict__ esrc4, int n_edges4) {
    int i = blockIdx.x * blockDim.x + threadIdx.x;
    if (i < n_edges4) {
        int4 s = __ldg(&esrc4[i]);
        atomicAdd(&g_cnt[s.x], 1);
        atomicAdd(&g_cnt[s.y], 1);
        atomicAdd(&g_cnt[s.z], 1);
        atomicAdd(&g_cnt[s.w], 1);
    }
}

// Local exclusive scan via shuffles; block base from one atomicAdd on g_total
// (arrival-ordered regions: disjoint + sized is all accum needs). Resets g_cnt.
__global__ __launch_bounds__(SCAN_CHUNK) void k_scan(int n) {
    __shared__ int warp_sum[32];
    __shared__ int s_base;
    int t = threadIdx.x;
    int lane = t & 31, w = t >> 5;
    int i = blockIdx.x * SCAN_CHUNK + t;

    int v = 0;
    if (i < n) { v = g_cnt[i]; g_cnt[i] = 0; }

    int x = v;
    #pragma unroll
    for (int off = 1; off < 32; off <<= 1) {
        int y = __shfl_up_sync(0xffffffff, x, off);
        if (lane >= off) x += y;
    }
    if (lane == 31) warp_sum[w] = x;
    __syncthreads();

    if (w == 0) {
        int ws = warp_sum[lane];
        int z = ws;
        #pragma unroll
        for (int off = 1; off < 32; off <<= 1) {
            int y = __shfl_up_sync(0xffffffff, z, off);
            if (lane >= off) z += y;
        }
        warp_sum[lane] = z - ws;
        if (lane == 31) s_base = (int)atomicAdd(&g_total, (unsigned)z);
    }
    __syncthreads();

    if (i < n) {
        int start = s_base + warp_sum[w] + (x - v);
        g_desc[i]   = make_int2(start, v);
        g_cursor[i] = start;
    }
}

__global__ void k_scatter(const int4* __restrict__ esrc4,
                          const int4* __restrict__ edst4,
                          const float4* __restrict__ ew4,
                          int n_edges4) {
    int i = blockIdx.x * blockDim.x + threadIdx.x;
    if (i >= n_edges4) return;
    int4   s = __ldg(&esrc4[i]);
    int4   d = __ldg(&edst4[i]);
    float4 w = __ldg(&ew4[i]);
    int p0 = atomicAdd(&g_cursor[s.x], 1);
    int p1 = atomicAdd(&g_cursor[s.y], 1);
    int p2 = atomicAdd(&g_cursor[s.z], 1);
    int p3 = atomicAdd(&g_cursor[s.w], 1);
    g_edge[p0] = make_float2(__int_as_float(d.x), w.x);
    g_edge[p1] = make_float2(__int_as_float(d.y), w.y);
    g_edge[p2] = make_float2(__int_as_float(d.z), w.z);
    g_edge[p3] = make_float2(__int_as_float(d.w), w.w);
}

// ONE WARP PER NODE: 32 lanes x float2 = 256B/row, zero intra-warp divergence
// (loop trip count == this node's degree for every lane). Unroll-2 + prefetch.
__global__ __launch_bounds__(256, 8) void k_accum(const float* __restrict__ feat,
                                                  float* __restrict__ out,
                                                  int n_nodes) {
    int gid  = blockIdx.x * blockDim.x + threadIdx.x;
    int node = gid >> 5;
    int lane = gid & 31;
    if (gid == 0) g_total = 0;           // reset allocator for next replay
    if (node >= n_nodes) return;

    int2 dsc = __ldg(&g_desc[node]);     // {start, len}, warp-broadcast
    int beg = dsc.x;
    int end = dsc.x + dsc.y;

    const float2* feat2 = reinterpret_cast<const float2*>(feat);
    float2 acc = make_float2(0.f, 0.f);
    int j = beg;

    if (j + 1 < end) {
        float2 e0 = __ldg(&g_edge[j]);
        float2 e1 = __ldg(&g_edge[j + 1]);
        for (; j + 3 < end; j += 2) {
            float2 n0 = __ldg(&g_edge[j + 2]);
            float2 n1 = __ldg(&g_edge[j + 3]);
            float2 v0 = __ldg(&feat2[(__float_as_int(e0.x) << 5) + lane]);
            float2 v1 = __ldg(&feat2[(__float_as_int(e1.x) << 5) + lane]);
            acc.x += v0.x * e0.y + v1.x * e1.y;
            acc.y += v0.y * e0.y + v1.y * e1.y;
            e0 = n0; e1 = n1;
        }
        float2 v0 = __ldg(&feat2[(__float_as_int(e0.x) << 5) + lane]);
        float2 v1 = __ldg(&feat2[(__float_as_int(e1.x) << 5) + lane]);
        acc.x += v0.x * e0.y + v1.x * e1.y;
        acc.y += v0.y * e0.y + v1.y * e1.y;
        j += 2;
    }
    if (j < end) {
        float2 e0 = __ldg(&g_edge[j]);
        float2 v0 = __ldg(&feat2[(__float_as_int(e0.x) << 5) + lane]);
        acc.x += v0.x * e0.y;
        acc.y += v0.y * e0.y;
    }
    reinterpret_cast<float2*>(out)[((long long)node << 5) + lane] = acc;
}

extern "C" void kernel_launch(void* const* d_in, const int* in_sizes, int n_in,
                              void* d_out, int out_size)
{
    const float* feat = (const float*)d_in[0];
    const float* ew   = (const float*)d_in[1];
    const int*   esrc = (const int*)d_in[2];
    const int*   edst = (const int*)d_in[3];
    float*       out  = (float*)d_out;

    int n_edges  = in_sizes[1];
    int n_nodes  = out_size / 64;
    int nb       = (n_nodes + SCAN_CHUNK - 1) / SCAN_CHUNK;   // 98
    int n_edges4 = n_edges / 4;                               // E divisible by 4

    k_hist<<<(n_edges4 + 255) / 256, 256>>>((const int4*)esrc, n_edges4);
    k_scan<<<nb, SCAN_CHUNK>>>(n_nodes);
    k_scatter<<<(n_edges4 + 255) / 256, 256>>>((const int4*)esrc, (const int4*)edst,
                                               (const float4*)ew, n_edges4);

    long long total = (long long)n_nodes * 32;
    k_accum<<<(int)((total + 255) / 256), 256>>>(feat, out, n_nodes);
}

// round 15
// speedup vs baseline: 1.5442x; 1.1150x over previous
#include <cuda_runtime.h>
#include <cstdint>

// out[src] += feat[dst] * w    ; feat [N,64] f32, E=1e6, N=1e5
// 4-launch dense-CSR pipeline:
//   k_hist   : degree histogram; RECORDS each edge's within-node position
//   k_scan   : per-block scan; block base via ONE global atomicAdd (order-free)
//   k_scatter: ATOMIC-FREE permute: g_edge[start[src]+pos[e]] = (dst,w)
//   k_accum  : atomic-free gather+FMA, 16 lanes/node (converged R11 loop)
//
// Inputs: d_in[0]=feat f32[N*64], d_in[1]=ew f32[E],
//         d_in[2]=esrc i32[E],    d_in[3]=edst i32[E]

#define MAXN 100000
#define MAXE 1000000
#define SCAN_CHUNK 1024

__device__ int      g_cnt[MAXN];     // zero at entry (zero-init; k_scan resets)
__device__ int2     g_desc[MAXN];    // {start, len} per node
__device__ int      g_pos[MAXE];     // per-edge within-node position (from hist)
__device__ float2   g_edge[MAXE];    // dense; .x = __int_as_float(dst), .y = w
__device__ unsigned g_total;         // base allocator; accum resets

__global__ void k_hist(const int4* __restrict__ esrc4, int n_edges4) {
    int i = blockIdx.x * blockDim.x + threadIdx.x;
    if (i < n_edges4) {
        int4 s = __ldg(&esrc4[i]);
        int4 p;
        p.x = atomicAdd(&g_cnt[s.x], 1);
        p.y = atomicAdd(&g_cnt[s.y], 1);
        p.z = atomicAdd(&g_cnt[s.z], 1);
        p.w = atomicAdd(&g_cnt[s.w], 1);
        reinterpret_cast<int4*>(g_pos)[i] = p;   // keep the returned positions
    }
}

// Local exclusive scan via shuffles; block base from one atomicAdd on g_total
// (arrival-ordered regions: disjoint + sized is all accum needs). Resets g_cnt.
__global__ __launch_bounds__(SCAN_CHUNK) void k_scan(int n) {
    __shared__ int warp_sum[32];
    __shared__ int s_base;
    int t = threadIdx.x;
    int lane = t & 31, w = t >> 5;
    int i = blockIdx.x * SCAN_CHUNK + t;

    int v = 0;
    if (i < n) { v = g_cnt[i]; g_cnt[i] = 0; }

    int x = v;
    #pragma unroll
    for (int off = 1; off < 32; off <<= 1) {
        int y = __shfl_up_sync(0xffffffff, x, off);
        if (lane >= off) x += y;
    }
    if (lane == 31) warp_sum[w] = x;
    __syncthreads();

    if (w == 0) {
        int ws = warp_sum[lane];
        int z = ws;
        #pragma unroll
        for (int off = 1; off < 32; off <<= 1) {
            int y = __shfl_up_sync(0xffffffff, z, off);
            if (lane >= off) z += y;
        }
        warp_sum[lane] = z - ws;
        if (lane == 31) s_base = (int)atomicAdd(&g_total, (unsigned)z);
    }
    __syncthreads();

    if (i < n) {
        int start = s_base + warp_sum[w] + (x - v);
        g_desc[i] = make_int2(start, v);
    }
}

// Atomic-free: position = start[src] + pos[e]; pure streaming + random stores.
__global__ void k_scatter(const int4* __restrict__ esrc4,
                          const int4* __restrict__ edst4,
                          const float4* __restrict__ ew4,
                          int n_edges4) {
    int i = blockIdx.x * blockDim.x + threadIdx.x;
    if (i >= n_edges4) return;
    int4   s = __ldg(&esrc4[i]);
    int4   d = __ldg(&edst4[i]);
    float4 w = __ldg(&ew4[i]);
    int4   p = reinterpret_cast<const int4*>(g_pos)[i];
    g_edge[__ldg(&g_desc[s.x]).x + p.x] = make_float2(__int_as_float(d.x), w.x);
    g_edge[__ldg(&g_desc[s.y]).x + p.y] = make_float2(__int_as_float(d.y), w.y);
    g_edge[__ldg(&g_desc[s.z]).x + p.z] = make_float2(__int_as_float(d.z), w.z);
    g_edge[__ldg(&g_desc[s.w]).x + p.w] = make_float2(__int_as_float(d.w), w.w);
}

// 16 lanes per node, float4 lanes, unroll-2 with next-pair prefetch; 8 blk/SM.
// (Converged R11 loop -- do not modify.)
__global__ __launch_bounds__(256, 8) void k_accum(const float* __restrict__ feat,
                                                  float* __restrict__ out,
                                                  int n_nodes) {
    int gid  = blockIdx.x * blockDim.x + threadIdx.x;
    int node = gid >> 4;
    int lane = gid & 15;
    if (gid == 0) g_total = 0;          // reset allocator for next replay
    if (node >= n_nodes) return;

    int2 dsc = __ldg(&g_desc[node]);    // one 8B broadcast load: {start, len}
    int beg = dsc.x;
    int end = dsc.x + dsc.y;

    float4 acc = make_float4(0.f, 0.f, 0.f, 0.f);
    int j = beg;

    if (j + 1 < end) {
        float2 e0 = __ldg(&g_edge[j]);
        float2 e1 = __ldg(&g_edge[j + 1]);
        for (; j + 3 < end; j += 2) {
            float2 n0 = __ldg(&g_edge[j + 2]);
            float2 n1 = __ldg(&g_edge[j + 3]);
            const float4* r0 = reinterpret_cast<const float4*>(feat + (__float_as_int(e0.x) << 6));
            const float4* r1 = reinterpret_cast<const float4*>(feat + (__float_as_int(e1.x) << 6));
            float4 v0 = __ldg(&r0[lane]);
            float4 v1 = __ldg(&r1[lane]);
            acc.x += v0.x * e0.y + v1.x * e1.y;
            acc.y += v0.y * e0.y + v1.y * e1.y;
            acc.z += v0.z * e0.y + v1.z * e1.y;
            acc.w += v0.w * e0.y + v1.w * e1.y;
            e0 = n0; e1 = n1;
        }
        const float4* r0 = reinterpret_cast<const float4*>(feat + (__float_as_int(e0.x) << 6));
        const float4* r1 = reinterpret_cast<const float4*>(feat + (__float_as_int(e1.x) << 6));
        float4 v0 = __ldg(&r0[lane]);
        float4 v1 = __ldg(&r1[lane]);
        acc.x += v0.x * e0.y + v1.x * e1.y;
        acc.y += v0.y * e0.y + v1.y * e1.y;
        acc.z += v0.z * e0.y + v1.z * e1.y;
        acc.w += v0.w * e0.y + v1.w * e1.y;
        j += 2;
    }
    if (j < end) {
        float2 e0 = __ldg(&g_edge[j]);
        const float4* r0 = reinterpret_cast<const float4*>(feat + (__float_as_int(e0.x) << 6));
        float4 v0 = __ldg(&r0[lane]);
        acc.x += v0.x * e0.y;
        acc.y += v0.y * e0.y;
        acc.z += v0.z * e0.y;
        acc.w += v0.w * e0.y;
    }
    reinterpret_cast<float4*>(out + ((long long)node << 6))[lane] = acc;
}

extern "C" void kernel_launch(void* const* d_in, const int* in_sizes, int n_in,
                              void* d_out, int out_size)
{
    const float* feat = (const float*)d_in[0];
    const float* ew   = (const float*)d_in[1];
    const int*   esrc = (const int*)d_in[2];
    const int*   edst = (const int*)d_in[3];
    float*       out  = (float*)d_out;

    int n_edges  = in_sizes[1];
    int n_nodes  = out_size / 64;
    int nb       = (n_nodes + SCAN_CHUNK - 1) / SCAN_CHUNK;   // 98
    int n_edges4 = n_edges / 4;                               // E divisible by 4

    k_hist<<<(n_edges4 + 255) / 256, 256>>>((const int4*)esrc, n_edges4);
    k_scan<<<nb, SCAN_CHUNK>>>(n_nodes);
    k_scatter<<<(n_edges4 + 255) / 256, 256>>>((const int4*)esrc, (const int4*)edst,
                                               (const float4*)ew, n_edges4);

    long long total = (long long)n_nodes * 16;
    k_accum<<<(int)((total + 255) / 256), 256>>>(feat, out, n_nodes);
}